// round 9
// baseline (speedup 1.0000x reference)
#include <cuda_runtime.h>
#include <cuda_fp16.h>
#include <cstdint>

#define NN 50000
#define MPAD 50048
#define EE 800000
#define GG 64
#define RRL 3
#define RN (RRL * NN)
#define METAD 38
#define BN_EPS 1e-5f

// ---------------- scratch (device globals; no allocation; force 256B alignment ------
// (cp.async 16B requires 16B-aligned global addresses; __half arrays only guarantee 2)
__device__ __align__(256) __half g_Ah[MPAD * 800];    // agg segments + indicator chunk
__device__ __align__(256) __half g_Bh[256 * 1088];    // B: [256, Kpad] fp16 K-major
__device__ __align__(256) __half g_x16[MPAD * 128];   // input x fp16 (pad rows stay 0)
__device__ __align__(256) __half g_actA[MPAD * 256];  // ping (pre-BN activations)
__device__ __align__(256) __half g_actB[MPAD * 256];  // pong
__device__ __align__(256) float g_biasx[256];
__device__ __align__(256) int   g_cnt[RN];
__device__ __align__(256) int   g_off[RN];
__device__ __align__(256) int   g_cur[RN];
__device__ __align__(256) int   g_esrc[EE];
__device__ __align__(256) int   g_bsum[256];
__device__ __align__(256) float g_sum[256];
__device__ __align__(256) float g_sumsq[256];
__device__ __align__(256) float g_scale[256];
__device__ __align__(256) float g_shift[256];
__device__ __align__(256) float g_pool[GG * 256];
__device__ __align__(256) int   g_pcnt[GG];

// ---------------- PTX helpers ----------------
__device__ __forceinline__ uint32_t smem_u32(const void* p) {
    uint32_t a;
    asm("{ .reg .u64 t; cvta.to.shared.u64 t, %1; cvt.u32.u64 %0, t; }" : "=r"(a) : "l"(p));
    return a;
}
__device__ __forceinline__ void ldm4(uint32_t* r, uint32_t addr) {
    asm volatile("ldmatrix.sync.aligned.m8n8.x4.shared.b16 {%0,%1,%2,%3}, [%4];"
                 : "=r"(r[0]), "=r"(r[1]), "=r"(r[2]), "=r"(r[3]) : "r"(addr));
}
__device__ __forceinline__ void mma_f16(float* d, const uint32_t* a, const uint32_t* b) {
    asm volatile(
        "mma.sync.aligned.m16n8k16.row.col.f32.f16.f16.f32 "
        "{%0,%1,%2,%3}, {%4,%5,%6,%7}, {%8,%9}, {%0,%1,%2,%3};"
        : "+f"(d[0]), "+f"(d[1]), "+f"(d[2]), "+f"(d[3])
        : "r"(a[0]), "r"(a[1]), "r"(a[2]), "r"(a[3]), "r"(b[0]), "r"(b[1]));
}
#define CP_ASYNC16(dst, src) \
    asm volatile("cp.async.cg.shared.global [%0], [%1], 16;" ::"r"(dst), "l"(src))
#define CP_COMMIT() asm volatile("cp.async.commit_group;" ::: "memory")
#define CP_WAIT(n) asm volatile("cp.async.wait_group %0;" ::"n"(n) : "memory")
#define REDADD(p, v) \
    asm volatile("red.global.add.f32 [%0], %1;" ::"l"(p), "f"(v) : "memory")

__device__ __forceinline__ float4 ld_h4(const __half* p) {
    uint2 raw = *(const uint2*)p;
    __half2 h0 = *reinterpret_cast<__half2*>(&raw.x);
    __half2 h1 = *reinterpret_cast<__half2*>(&raw.y);
    float2 f0 = __half22float2(h0), f1 = __half22float2(h1);
    return make_float4(f0.x, f0.y, f1.x, f1.y);
}
__device__ __forceinline__ void st_h4(__half* p, float4 v) {
    uint2 raw;
    __half2 h0 = __floats2half2_rn(v.x, v.y);
    __half2 h1 = __floats2half2_rn(v.z, v.w);
    raw.x = *reinterpret_cast<uint32_t*>(&h0);
    raw.y = *reinterpret_cast<uint32_t*>(&h1);
    *(uint2*)p = raw;
}

// ---------------- utility kernels ----------------
__global__ void zero_f(float* p, int n) {
    for (int i = blockIdx.x * blockDim.x + threadIdx.x; i < n; i += gridDim.x * blockDim.x)
        p[i] = 0.f;
}
__global__ void zero_i(int* p, int n) {
    for (int i = blockIdx.x * blockDim.x + threadIdx.x; i < n; i += gridDim.x * blockDim.x)
        p[i] = 0;
}
__global__ void count_kernel(const int* __restrict__ ei, const int* __restrict__ et,
                             int* __restrict__ cnt) {
    int e = blockIdx.x * blockDim.x + threadIdx.x;
    if (e >= EE) return;
    atomicAdd(&cnt[et[e] * NN + ei[EE + e]], 1);
}
__global__ void conv_x(const float* __restrict__ x, __half* __restrict__ x16, int n) {
    int i = blockIdx.x * blockDim.x + threadIdx.x;
    if (i < n) {
        float2 v = ((const float2*)x)[i];
        ((__half2*)x16)[i] = __floats2half2_rn(v.x, v.y);
    }
}

// ---------------- CSR build ----------------
__global__ void scan1(const int* __restrict__ cnt, int* __restrict__ off,
                      int* __restrict__ bsum, int n) {
    __shared__ int sh[256];
    int tid = threadIdx.x;
    int base = blockIdx.x * 1024;
    int vals[4], tsum = 0;
#pragma unroll
    for (int j = 0; j < 4; j++) {
        int i = base + tid * 4 + j;
        vals[j] = (i < n) ? cnt[i] : 0;
        tsum += vals[j];
    }
    sh[tid] = tsum;
    __syncthreads();
    for (int d = 1; d < 256; d <<= 1) {
        int v = (tid >= d) ? sh[tid - d] : 0;
        __syncthreads();
        sh[tid] += v;
        __syncthreads();
    }
    int run = sh[tid] - tsum;
#pragma unroll
    for (int j = 0; j < 4; j++) {
        int i = base + tid * 4 + j;
        if (i < n) off[i] = run;
        run += vals[j];
    }
    if (tid == 255) bsum[blockIdx.x] = sh[255];
}
__global__ void scan2(int* __restrict__ bsum, int nb) {
    __shared__ int sh[256];
    int tid = threadIdx.x;
    int v = (tid < nb) ? bsum[tid] : 0;
    sh[tid] = v;
    __syncthreads();
    for (int d = 1; d < 256; d <<= 1) {
        int u = (tid >= d) ? sh[tid - d] : 0;
        __syncthreads();
        sh[tid] += u;
        __syncthreads();
    }
    if (tid < nb) bsum[tid] = sh[tid] - v;
}
__global__ void scan3(int* __restrict__ off, const int* __restrict__ bsum, int n) {
    int i = blockIdx.x * blockDim.x + threadIdx.x;
    if (i < n) off[i] += bsum[i >> 10];
}
__global__ void fill_kernel(const int* __restrict__ ei, const int* __restrict__ et,
                            const int* __restrict__ off, int* __restrict__ cur,
                            int* __restrict__ esrc) {
    int e = blockIdx.x * blockDim.x + threadIdx.x;
    if (e >= EE) return;
    int seg = et[e] * NN + ei[EE + e];
    int p = off[seg] + atomicAdd(&cur[seg], 1);
    esrc[p] = ei[e];
}

// ---------------- aggregation: warp per (r,dst), raw mean + indicator chunk ----------
__global__ void __launch_bounds__(256)
agg_kernel(const int* __restrict__ esrc, const int* __restrict__ off,
           const int* __restrict__ cnt, const __half* __restrict__ act,
           __half* __restrict__ Ah, int din, int actStride, int Kseg, int aggW) {
    int s = blockIdx.x * 8 + (threadIdx.x >> 5);
    if (s >= RN) return;
    int lane = threadIdx.x & 31;
    int r = s / NN, dst = s - r * NN;
    int st = off[s], c_ = cnt[s];
    int e = st + c_;
    __half* out = Ah + (size_t)dst * aggW + (size_t)r * Kseg;
    for (int c0 = lane * 4; c0 < Kseg; c0 += 128) {
        float4 a = make_float4(0.f, 0.f, 0.f, 0.f);
        if (c0 < din && c_ > 0) {
            float4 b = make_float4(0.f, 0.f, 0.f, 0.f);
            int i = st;
            for (; i + 2 <= e; i += 2) {
                int s0 = esrc[i], s1 = esrc[i + 1];
                float4 v0 = ld_h4(act + (size_t)s0 * actStride + c0);
                float4 v1 = ld_h4(act + (size_t)s1 * actStride + c0);
                a.x += v0.x; a.y += v0.y; a.z += v0.z; a.w += v0.w;
                b.x += v1.x; b.y += v1.y; b.z += v1.z; b.w += v1.w;
            }
            if (i < e) {
                float4 v0 = ld_h4(act + (size_t)esrc[i] * actStride + c0);
                a.x += v0.x; a.y += v0.y; a.z += v0.z; a.w += v0.w;
            }
            a.x += b.x; a.y += b.y; a.z += b.z; a.w += b.w;
            float inv = 1.0f / (float)c_;
            a.x *= inv; a.y *= inv; a.z *= inv; a.w *= inv;
        }
        st_h4(out + c0, a);
    }
    // indicator chunk: col r = [cnt>0]; r==0 warp zeroes cols 3..31
    __half* ind = Ah + (size_t)dst * aggW + 3 * Kseg;
    if (lane == 0) ind[r] = __float2half(c_ > 0 ? 1.f : 0.f);
    if (r == 0 && lane >= 3) ind[lane] = __float2half(0.f);
}

// ---------------- B build: scale-folded [Rw; W0; W1; W2] + indicator rows ----------
__global__ void convB_h(const float* __restrict__ Wrel, const float* __restrict__ Wroot,
                        const float* __restrict__ scale, const float* __restrict__ shift,
                        __half* __restrict__ Bh, int din, int Kseg, int Kpad, int dout) {
    int idx = blockIdx.x * blockDim.x + threadIdx.x;
    if (idx >= 256 * Kpad) return;
    int n = idx / Kpad;
    int k = idx - n * Kpad;
    int kInd = 4 * Kseg;
    float v = 0.f;
    if (n < dout) {
        if (k < kInd) {
            int seg = k / Kseg, kk = k - seg * Kseg;
            if (kk < din) {
                float w = (seg == 0) ? Wroot[(size_t)kk * dout + n]
                                     : Wrel[((size_t)(seg - 1) * din + kk) * dout + n];
                if (scale) w *= scale[kk];
                v = w;
            }
        } else {
            int r = k - kInd;
            if (r < 3 && shift) {
                float a = 0.f;
                for (int kk = 0; kk < din; kk++)
                    a += shift[kk] * Wrel[((size_t)r * din + kk) * dout + n];
                v = a;
            }
        }
    }
    Bh[idx] = __float2half(v);
}

// ---------------- prep: biasx = b + shift@Rw; zero stat accumulators ----------------
__global__ void prep_kernel(const float* __restrict__ b, const float* __restrict__ Rw,
                            const float* __restrict__ shift, float* __restrict__ biasx,
                            float* __restrict__ sum, float* __restrict__ sumsq, int din,
                            int dout) {
    int t = threadIdx.x;  // 256
    sum[t] = 0.f;
    sumsq[t] = 0.f;
    if (t < dout) {
        float a = b[t];
        if (shift)
            for (int k = 0; k < din; k++) a += shift[k] * Rw[(size_t)k * dout + t];
        biasx[t] = a;
    }
}

// ---------------- fp16 mma GEMM: 128x256 tile, dual-pointer A, fused BN stats --------
#define GSTR 40
#define ATILE_B (128 * GSTR * 2)   // 10240
#define BTILE_B (256 * GSTR * 2)   // 20480
#define STG_B (ATILE_B + BTILE_B)  // 30720
#define GSMEM (2 * STG_B)          // 61440

__global__ void __launch_bounds__(512, 1)
gemm_h(const __half* __restrict__ Aroot, const __half* __restrict__ Aagg,
       const __half* __restrict__ B, __half* __restrict__ actOut,
       const float* __restrict__ biasx, float* __restrict__ sum, float* __restrict__ sumsq,
       int Kseg, int rootStride, int aggW, int Kpad, int dout, int strideOut) {
    extern __shared__ char smem[];
    uint32_t sb = smem_u32(smem);
    const int tid = threadIdx.x;
    const int wid = tid >> 5, lane = tid & 31;
    const int bm = blockIdx.y * 128;
    const int wm = wid >> 2;   // 0..3 : 32-row slab
    const int wn = wid & 3;    // 0..3 : 64-col slab

    const int rA = (lane & 7) + ((lane >> 3) & 1) * 8;
    const int kA = (lane >> 4) * 8;
    const int rB = (lane & 7) + ((lane >> 4) & 1) * 8;
    const int kB = ((lane >> 3) & 1) * 8;

    float acc[2][8][4];
#pragma unroll
    for (int mi = 0; mi < 2; mi++)
#pragma unroll
        for (int ni = 0; ni < 8; ni++)
#pragma unroll
            for (int e = 0; e < 4; e++) acc[mi][ni][e] = 0.f;

    const int nIter = Kpad >> 5;
    const size_t KpadB = (size_t)Kpad * 2;

#define LOAD_STAGE(it, stg)                                                              \
    {                                                                                    \
        int kt = (it)*32;                                                                \
        const char* abase;                                                               \
        size_t rstride;                                                                  \
        if (kt < Kseg) {                                                                 \
            abase = (const char*)Aroot + (size_t)kt * 2;                                 \
            rstride = (size_t)rootStride * 2;                                            \
        } else {                                                                         \
            abase = (const char*)Aagg + (size_t)(kt - Kseg) * 2;                         \
            rstride = (size_t)aggW * 2;                                                  \
        }                                                                                \
        uint32_t sdst = sb + (stg)*STG_B;                                                \
        {                                                                                \
            int row = tid >> 2, c = tid & 3;                                             \
            CP_ASYNC16(sdst + row * 80 + c * 16,                                         \
                       abase + (size_t)(bm + row) * rstride + c * 16);                   \
        }                                                                                \
        const char* bbase = (const char*)B + (size_t)kt * 2;                             \
        {                                                                                \
            int row = tid >> 2, c = tid & 3;                                             \
            CP_ASYNC16(sdst + ATILE_B + row * 80 + c * 16,                               \
                       bbase + (size_t)row * KpadB + c * 16);                            \
        }                                                                                \
        {                                                                                \
            int row = (tid >> 2) + 128, c = tid & 3;                                     \
            CP_ASYNC16(sdst + ATILE_B + row * 80 + c * 16,                               \
                       bbase + (size_t)row * KpadB + c * 16);                            \
        }                                                                                \
    }

    LOAD_STAGE(0, 0);
    CP_COMMIT();

    for (int i = 0; i < nIter; i++) {
        if (i + 1 < nIter) {
            LOAD_STAGE(i + 1, (i + 1) & 1);
            CP_COMMIT();
            CP_WAIT(1);
        } else {
            CP_WAIT(0);
        }
        __syncthreads();

        uint32_t st = sb + (i & 1) * STG_B;
        uint32_t sA_t = st + ((wm * 32 + rA) * GSTR + kA) * 2;
        uint32_t sB_t = st + ATILE_B + ((wn * 64 + rB) * GSTR + kB) * 2;

#pragma unroll
        for (int kk = 0; kk < 2; kk++) {
            uint32_t koff = kk * 32;
            uint32_t Af[2][4], Bf[8][2];
            ldm4(Af[0], sA_t + koff);
            ldm4(Af[1], sA_t + 16 * GSTR * 2 + koff);
#pragma unroll
            for (int j = 0; j < 4; j++) {
                uint32_t t[4];
                ldm4(t, sB_t + j * 16 * GSTR * 2 + koff);
                Bf[2 * j][0] = t[0]; Bf[2 * j][1] = t[1];
                Bf[2 * j + 1][0] = t[2]; Bf[2 * j + 1][1] = t[3];
            }
#pragma unroll
            for (int mi = 0; mi < 2; mi++)
#pragma unroll
                for (int ni = 0; ni < 8; ni++) mma_f16(acc[mi][ni], Af[mi], Bf[ni]);
        }
        __syncthreads();
    }

    // epilogue: store fp16 (+biasx, zero-pad), fused BN stats via shuffle + red.add
    const int grp = lane >> 2, q = lane & 3;
#pragma unroll
    for (int ni = 0; ni < 8; ni++) {
        int gc = wn * 64 + ni * 8 + q * 2;
        float bx0 = (gc < dout) ? biasx[gc] : 0.f;
        float bx1 = (gc + 1 < dout) ? biasx[gc + 1] : 0.f;
        float t0 = 0.f, t1 = 0.f, u0 = 0.f, u1 = 0.f;
#pragma unroll
        for (int mi = 0; mi < 2; mi++) {
#pragma unroll
            for (int hf = 0; hf < 2; hf++) {
                int m = bm + wm * 32 + mi * 16 + grp + hf * 8;
                if (m >= NN) continue;
                float o0 = (gc < dout) ? acc[mi][ni][hf * 2] + bx0 : 0.f;
                float o1 = (gc + 1 < dout) ? acc[mi][ni][hf * 2 + 1] + bx1 : 0.f;
                if (gc < strideOut)
                    *(__half2*)(actOut + (size_t)m * strideOut + gc) =
                        __floats2half2_rn(o0, o1);
                t0 += o0; u0 += o0 * o0;
                t1 += o1; u1 += o1 * o1;
            }
        }
#pragma unroll
        for (int d = 4; d < 32; d <<= 1) {
            t0 += __shfl_xor_sync(0xffffffffu, t0, d);
            t1 += __shfl_xor_sync(0xffffffffu, t1, d);
            u0 += __shfl_xor_sync(0xffffffffu, u0, d);
            u1 += __shfl_xor_sync(0xffffffffu, u1, d);
        }
        if (grp == 0 && gc < dout) {
            REDADD(&sum[gc], t0);
            REDADD(&sumsq[gc], u0);
            if (gc + 1 < dout) {
                REDADD(&sum[gc + 1], t1);
                REDADD(&sumsq[gc + 1], u1);
            }
        }
    }
}

// ---------------- BN finalize ----------------
__global__ void bn_finalize(const float* __restrict__ sum, const float* __restrict__ sumsq,
                            const float* __restrict__ g, const float* __restrict__ bb,
                            float* __restrict__ scale, float* __restrict__ shift, int n) {
    int c = threadIdx.x;
    float invn = 1.0f / (float)n;
    float mu = sum[c] * invn;
    float var = sumsq[c] * invn - mu * mu;
    float sc = g[c] * rsqrtf(var + BN_EPS);
    scale[c] = sc;
    shift[c] = bb[c] - mu * sc;
}

// ---------------- pooling (final BN fused) ----------------
__global__ void __launch_bounds__(256)
pool_kernel(const __half* __restrict__ x, const int* __restrict__ batch,
            const float* __restrict__ scale, const float* __restrict__ shift,
            float* __restrict__ pool, int* __restrict__ pcnt) {
    int row = blockIdx.x * 8 + (threadIdx.x >> 5);
    if (row >= NN) return;
    int lane = threadIdx.x & 31;
    int g = batch[row];
    const __half* in = x + (size_t)row * 256;
    float* op = pool + (size_t)g * 256;
    for (int c = lane * 4; c < 256; c += 128) {
        float4 v = ld_h4(in + c);
        v.x = v.x * scale[c] + shift[c];
        v.y = v.y * scale[c + 1] + shift[c + 1];
        v.z = v.z * scale[c + 2] + shift[c + 2];
        v.w = v.w * scale[c + 3] + shift[c + 3];
        asm volatile("red.global.add.v4.f32 [%0], {%1,%2,%3,%4};" ::"l"(op + c),
                     "f"(v.x), "f"(v.y), "f"(v.z), "f"(v.w)
                     : "memory");
    }
    if (lane == 0) atomicAdd(&pcnt[g], 1);
}

// ---------------- final MLP head ----------------
__global__ void final_kernel(const float* __restrict__ pool, const int* __restrict__ pcnt,
                             const float* __restrict__ meta, const float* __restrict__ l1w,
                             const float* __restrict__ l1b, const float* __restrict__ l2w,
                             const float* __restrict__ l2b, float* __restrict__ out) {
    __shared__ float cv[256 + METAD];
    __shared__ float red[128];
    int g = blockIdx.x;
    int t = threadIdx.x;
    float invc = 1.0f / fmaxf((float)pcnt[g], 1.0f);
    for (int c = t; c < 256 + METAD; c += 128)
        cv[c] = (c < 256) ? pool[g * 256 + c] * invc : meta[g * METAD + (c - 256)];
    __syncthreads();
    float val = 0.f;
    if (t < 100) {
        float a = l1b[t];
        for (int i = 0; i < 256 + METAD; i++) a += cv[i] * l1w[i * 100 + t];
        val = a * l2w[t];
    }
    red[t] = val;
    __syncthreads();
    for (int s = 64; s > 0; s >>= 1) {
        if (t < s) red[t] += red[t + s];
        __syncthreads();
    }
    if (t == 0) out[g] = red[0] + l2b[0];
}

// ---------------- host driver ----------------
struct Ptrs {
    __half *Ah, *Bh, *x16, *actA, *actB;
    float *biasx, *sum, *sumsq, *scale, *shift, *pool;
    int *cnt, *off, *cur, *esrc, *bsum, *pcnt;
};

static void run_layer(const __half* actIn, int actStride, const float* scaleIn,
                      const float* shiftIn, int din, int Kseg, int dout, int strideOut,
                      const float* W, const float* Rw, const float* b, const float* gm,
                      const float* bt, __half* actOut, const Ptrs& P) {
    int aggW = 3 * Kseg + 32;
    int Kpad = 4 * Kseg + 32;
    agg_kernel<<<(RN + 7) / 8, 256>>>(P.esrc, P.off, P.cnt, actIn, P.Ah, din, actStride,
                                      Kseg, aggW);
    convB_h<<<(256 * Kpad + 255) / 256, 256>>>(W, Rw, scaleIn, shiftIn, P.Bh, din, Kseg,
                                               Kpad, dout);
    prep_kernel<<<1, 256>>>(b, Rw, shiftIn, P.biasx, P.sum, P.sumsq, din, dout);
    dim3 grid(1, MPAD / 128);
    gemm_h<<<grid, 512, GSMEM>>>(actIn, P.Ah, P.Bh, actOut, P.biasx, P.sum, P.sumsq, Kseg,
                                 actStride, aggW, Kpad, dout, strideOut);
    bn_finalize<<<1, dout>>>(P.sum, P.sumsq, gm, bt, P.scale, P.shift, NN);
}

extern "C" void kernel_launch(void* const* d_in, const int* in_sizes, int n_in,
                              void* d_out, int out_size) {
    const float* x = (const float*)d_in[0];
    const int* ei = (const int*)d_in[2];
    const int* et = (const int*)d_in[3];
    const float* meta = (const float*)d_in[4];
    const int* batch = (const int*)d_in[5];
    const float* W[4];
    const float* Rw[4];
    const float* b[4];
    const float* gm[4];
    const float* bt[4];
    int idx = 6;
    for (int l = 0; l < 4; l++) {
        W[l] = (const float*)d_in[idx++];
        Rw[l] = (const float*)d_in[idx++];
        b[l] = (const float*)d_in[idx++];
        gm[l] = (const float*)d_in[idx++];
        bt[l] = (const float*)d_in[idx++];
    }
    const float* l1w = (const float*)d_in[26];
    const float* l1b = (const float*)d_in[27];
    const float* l2w = (const float*)d_in[28];
    const float* l2b = (const float*)d_in[29];
    float* out = (float*)d_out;

    Ptrs P;
    cudaGetSymbolAddress((void**)&P.Ah, g_Ah);
    cudaGetSymbolAddress((void**)&P.Bh, g_Bh);
    cudaGetSymbolAddress((void**)&P.x16, g_x16);
    cudaGetSymbolAddress((void**)&P.actA, g_actA);
    cudaGetSymbolAddress((void**)&P.actB, g_actB);
    cudaGetSymbolAddress((void**)&P.biasx, g_biasx);
    cudaGetSymbolAddress((void**)&P.cnt, g_cnt);
    cudaGetSymbolAddress((void**)&P.off, g_off);
    cudaGetSymbolAddress((void**)&P.cur, g_cur);
    cudaGetSymbolAddress((void**)&P.esrc, g_esrc);
    cudaGetSymbolAddress((void**)&P.bsum, g_bsum);
    cudaGetSymbolAddress((void**)&P.sum, g_sum);
    cudaGetSymbolAddress((void**)&P.sumsq, g_sumsq);
    cudaGetSymbolAddress((void**)&P.scale, g_scale);
    cudaGetSymbolAddress((void**)&P.shift, g_shift);
    cudaGetSymbolAddress((void**)&P.pool, g_pool);
    cudaGetSymbolAddress((void**)&P.pcnt, g_pcnt);

    cudaFuncSetAttribute(gemm_h, cudaFuncAttributeMaxDynamicSharedMemorySize, GSMEM);

    // CSR build (input-constant per call)
    zero_i<<<256, 256>>>(P.cnt, RN);
    zero_i<<<256, 256>>>(P.cur, RN);
    count_kernel<<<(EE + 255) / 256, 256>>>(ei, et, P.cnt);
    int nb = (RN + 1023) / 1024;  // 147
    scan1<<<nb, 256>>>(P.cnt, P.off, P.bsum, RN);
    scan2<<<1, 256>>>(P.bsum, nb);
    scan3<<<(RN + 255) / 256, 256>>>(P.off, P.bsum, RN);
    fill_kernel<<<(EE + 255) / 256, 256>>>(ei, et, P.off, P.cur, P.esrc);

    // input -> fp16 once (pad rows of g_x16 stay 0)
    conv_x<<<(NN * 64 + 255) / 256, 256>>>(x, P.x16, NN * 64);

    // 4 RGCN layers (aggregate-first, BN folded into B + indicator chunk)
    //        actIn   stride  scale    shift    din  Kseg dout strideOut
    run_layer(P.x16,  128,    nullptr, nullptr, 128, 128, 100, 128, W[0], Rw[0], b[0],
              gm[0], bt[0], P.actA, P);
    run_layer(P.actA, 128,    P.scale, P.shift, 100, 128, 256, 256, W[1], Rw[1], b[1],
              gm[1], bt[1], P.actB, P);
    run_layer(P.actB, 256,    P.scale, P.shift, 256, 256, 256, 256, W[2], Rw[2], b[2],
              gm[2], bt[2], P.actA, P);
    run_layer(P.actA, 256,    P.scale, P.shift, 256, 256, 256, 256, W[3], Rw[3], b[3],
              gm[3], bt[3], P.actB, P);

    // global mean pool (final BN fused) + MLP head
    zero_f<<<64, 256>>>(P.pool, GG * 256);
    zero_i<<<1, 64>>>(P.pcnt, GG);
    pool_kernel<<<(NN + 7) / 8, 256>>>(P.actB, batch, P.scale, P.shift, P.pool, P.pcnt);
    final_kernel<<<GG, 128>>>(P.pool, P.pcnt, meta, l1w, l1b, l2w, l2b, out);
}

// round 11
// speedup vs baseline: 1.2129x; 1.2129x over previous
#include <cuda_runtime.h>
#include <cuda_fp16.h>
#include <cstdint>

#define NN 50000
#define MPAD 50048
#define EE 800000
#define GG 64
#define RRL 3
#define RN (RRL * NN)
#define METAD 38
#define BN_EPS 1e-5f

// ---------------- scratch (device globals; no allocation; 256B aligned) ----------------
__device__ __align__(256) __half g_Ah[MPAD * 800];    // agg segments + indicator chunk
__device__ __align__(256) __half g_Bh[256 * 1088];    // B: [256, Kpad] fp16 K-major
__device__ __align__(256) __half g_x16[MPAD * 128];   // input x fp16 (pad rows stay 0)
__device__ __align__(256) __half g_actA[MPAD * 256];  // ping (pre-BN activations)
__device__ __align__(256) __half g_actB[MPAD * 256];  // pong
__device__ __align__(256) float g_biasx[256];
__device__ __align__(256) int   g_cnt[RN];
__device__ __align__(256) int   g_off[RN];
__device__ __align__(256) int   g_cur[RN];
__device__ __align__(256) int   g_esrc[EE];
__device__ __align__(256) int   g_bsum[256];
__device__ __align__(256) float g_sum[256];
__device__ __align__(256) float g_sumsq[256];
__device__ __align__(256) float g_scale[256];
__device__ __align__(256) float g_shift[256];
__device__ __align__(256) float g_pool[GG * 256];
__device__ __align__(256) int   g_pcnt[GG];

// ---------------- PTX helpers ----------------
__device__ __forceinline__ uint32_t smem_u32(const void* p) {
    uint32_t a;
    asm("{ .reg .u64 t; cvta.to.shared.u64 t, %1; cvt.u32.u64 %0, t; }" : "=r"(a) : "l"(p));
    return a;
}
__device__ __forceinline__ void ldm4(uint32_t* r, uint32_t addr) {
    asm volatile("ldmatrix.sync.aligned.m8n8.x4.shared.b16 {%0,%1,%2,%3}, [%4];"
                 : "=r"(r[0]), "=r"(r[1]), "=r"(r[2]), "=r"(r[3]) : "r"(addr));
}
__device__ __forceinline__ void mma_f16(float* d, const uint32_t* a, const uint32_t* b) {
    asm volatile(
        "mma.sync.aligned.m16n8k16.row.col.f32.f16.f16.f32 "
        "{%0,%1,%2,%3}, {%4,%5,%6,%7}, {%8,%9}, {%0,%1,%2,%3};"
        : "+f"(d[0]), "+f"(d[1]), "+f"(d[2]), "+f"(d[3])
        : "r"(a[0]), "r"(a[1]), "r"(a[2]), "r"(a[3]), "r"(b[0]), "r"(b[1]));
}
#define CP_ASYNC16(dst, src) \
    asm volatile("cp.async.cg.shared.global [%0], [%1], 16;" ::"r"(dst), "l"(src))
#define CP_COMMIT() asm volatile("cp.async.commit_group;" ::: "memory")
#define CP_WAIT(n) asm volatile("cp.async.wait_group %0;" ::"n"(n) : "memory")
#define REDADD(p, v) \
    asm volatile("red.global.add.f32 [%0], %1;" ::"l"(p), "f"(v) : "memory")

__device__ __forceinline__ float4 ld_h4(const __half* p) {
    uint2 raw = *(const uint2*)p;
    __half2 h0 = *reinterpret_cast<__half2*>(&raw.x);
    __half2 h1 = *reinterpret_cast<__half2*>(&raw.y);
    float2 f0 = __half22float2(h0), f1 = __half22float2(h1);
    return make_float4(f0.x, f0.y, f1.x, f1.y);
}
__device__ __forceinline__ void st_h4(__half* p, float4 v) {
    uint2 raw;
    __half2 h0 = __floats2half2_rn(v.x, v.y);
    __half2 h1 = __floats2half2_rn(v.z, v.w);
    raw.x = *reinterpret_cast<uint32_t*>(&h0);
    raw.y = *reinterpret_cast<uint32_t*>(&h1);
    *(uint2*)p = raw;
}

// ---------------- utility kernels ----------------
__global__ void zero_f(float* p, int n) {
    for (int i = blockIdx.x * blockDim.x + threadIdx.x; i < n; i += gridDim.x * blockDim.x)
        p[i] = 0.f;
}
__global__ void zero_i(int* p, int n) {
    for (int i = blockIdx.x * blockDim.x + threadIdx.x; i < n; i += gridDim.x * blockDim.x)
        p[i] = 0;
}
__global__ void count_kernel(const int* __restrict__ ei, const int* __restrict__ et,
                             int* __restrict__ cnt) {
    int e = blockIdx.x * blockDim.x + threadIdx.x;
    if (e >= EE) return;
    atomicAdd(&cnt[et[e] * NN + ei[EE + e]], 1);
}
__global__ void conv_x(const float* __restrict__ x, __half* __restrict__ x16, int n) {
    int i = blockIdx.x * blockDim.x + threadIdx.x;
    if (i < n) {
        float2 v = ((const float2*)x)[i];
        ((__half2*)x16)[i] = __floats2half2_rn(v.x, v.y);
    }
}

// ---------------- CSR build ----------------
__global__ void scan1(const int* __restrict__ cnt, int* __restrict__ off,
                      int* __restrict__ bsum, int n) {
    __shared__ int sh[256];
    int tid = threadIdx.x;
    int base = blockIdx.x * 1024;
    int vals[4], tsum = 0;
#pragma unroll
    for (int j = 0; j < 4; j++) {
        int i = base + tid * 4 + j;
        vals[j] = (i < n) ? cnt[i] : 0;
        tsum += vals[j];
    }
    sh[tid] = tsum;
    __syncthreads();
    for (int d = 1; d < 256; d <<= 1) {
        int v = (tid >= d) ? sh[tid - d] : 0;
        __syncthreads();
        sh[tid] += v;
        __syncthreads();
    }
    int run = sh[tid] - tsum;
#pragma unroll
    for (int j = 0; j < 4; j++) {
        int i = base + tid * 4 + j;
        if (i < n) off[i] = run;
        run += vals[j];
    }
    if (tid == 255) bsum[blockIdx.x] = sh[255];
}
__global__ void scan2(int* __restrict__ bsum, int nb) {
    __shared__ int sh[256];
    int tid = threadIdx.x;
    int v = (tid < nb) ? bsum[tid] : 0;
    sh[tid] = v;
    __syncthreads();
    for (int d = 1; d < 256; d <<= 1) {
        int u = (tid >= d) ? sh[tid - d] : 0;
        __syncthreads();
        sh[tid] += u;
        __syncthreads();
    }
    if (tid < nb) bsum[tid] = sh[tid] - v;
}
__global__ void scan3(int* __restrict__ off, const int* __restrict__ bsum, int n) {
    int i = blockIdx.x * blockDim.x + threadIdx.x;
    if (i < n) off[i] += bsum[i >> 10];
}
__global__ void fill_kernel(const int* __restrict__ ei, const int* __restrict__ et,
                            const int* __restrict__ off, int* __restrict__ cur,
                            int* __restrict__ esrc) {
    int e = blockIdx.x * blockDim.x + threadIdx.x;
    if (e >= EE) return;
    int seg = et[e] * NN + ei[EE + e];
    int p = off[seg] + atomicAdd(&cur[seg], 1);
    esrc[p] = ei[e];
}

// ---------------- aggregation: warp per (r,dst), raw mean + indicator chunk ----------
__global__ void __launch_bounds__(256)
agg_kernel(const int* __restrict__ esrc, const int* __restrict__ off,
           const int* __restrict__ cnt, const __half* __restrict__ act,
           __half* __restrict__ Ah, int din, int actStride, int Kseg, int aggW) {
    int s = blockIdx.x * 8 + (threadIdx.x >> 5);
    if (s >= RN) return;
    int lane = threadIdx.x & 31;
    int r = s / NN, dst = s - r * NN;
    int st = off[s], c_ = cnt[s];
    int e = st + c_;
    __half* out = Ah + (size_t)dst * aggW + (size_t)r * Kseg;
    for (int c0 = lane * 4; c0 < Kseg; c0 += 128) {
        float4 a = make_float4(0.f, 0.f, 0.f, 0.f);
        if (c0 < din && c_ > 0) {
            float4 b = make_float4(0.f, 0.f, 0.f, 0.f);
            int i = st;
            for (; i + 2 <= e; i += 2) {
                int s0 = esrc[i], s1 = esrc[i + 1];
                float4 v0 = ld_h4(act + (size_t)s0 * actStride + c0);
                float4 v1 = ld_h4(act + (size_t)s1 * actStride + c0);
                a.x += v0.x; a.y += v0.y; a.z += v0.z; a.w += v0.w;
                b.x += v1.x; b.y += v1.y; b.z += v1.z; b.w += v1.w;
            }
            if (i < e) {
                float4 v0 = ld_h4(act + (size_t)esrc[i] * actStride + c0);
                a.x += v0.x; a.y += v0.y; a.z += v0.z; a.w += v0.w;
            }
            a.x += b.x; a.y += b.y; a.z += b.z; a.w += b.w;
            float inv = 1.0f / (float)c_;
            a.x *= inv; a.y *= inv; a.z *= inv; a.w *= inv;
        }
        st_h4(out + c0, a);
    }
    // indicator chunk: col r = [cnt>0]; r==0 warp zeroes cols 3..31
    __half* ind = Ah + (size_t)dst * aggW + 3 * Kseg;
    if (lane == 0) ind[r] = __float2half(c_ > 0 ? 1.f : 0.f);
    if (r == 0 && lane >= 3) ind[lane] = __float2half(0.f);
}

// ---------------- B build: scale-folded [Rw; W0; W1; W2] + indicator rows ----------
__global__ void convB_h(const float* __restrict__ Wrel, const float* __restrict__ Wroot,
                        const float* __restrict__ scale, const float* __restrict__ shift,
                        __half* __restrict__ Bh, int din, int Kseg, int Kpad, int dout) {
    int idx = blockIdx.x * blockDim.x + threadIdx.x;
    if (idx >= 256 * Kpad) return;
    int n = idx / Kpad;
    int k = idx - n * Kpad;
    int kInd = 4 * Kseg;
    float v = 0.f;
    if (n < dout) {
        if (k < kInd) {
            int seg = k / Kseg, kk = k - seg * Kseg;
            if (kk < din) {
                float w = (seg == 0) ? Wroot[(size_t)kk * dout + n]
                                     : Wrel[((size_t)(seg - 1) * din + kk) * dout + n];
                if (scale) w *= scale[kk];
                v = w;
            }
        } else {
            int r = k - kInd;
            if (r < 3 && shift) {
                float a = 0.f;
                for (int kk = 0; kk < din; kk++)
                    a += shift[kk] * Wrel[((size_t)r * din + kk) * dout + n];
                v = a;
            }
        }
    }
    Bh[idx] = __float2half(v);
}

// ---------------- prep: biasx = b + shift@Rw; zero stat accumulators ----------------
__global__ void prep_kernel(const float* __restrict__ b, const float* __restrict__ Rw,
                            const float* __restrict__ shift, float* __restrict__ biasx,
                            float* __restrict__ sum, float* __restrict__ sumsq, int din,
                            int dout) {
    int t = threadIdx.x;  // 256
    sum[t] = 0.f;
    sumsq[t] = 0.f;
    if (t < dout) {
        float a = b[t];
        if (shift)
            for (int k = 0; k < din; k++) a += shift[k] * Rw[(size_t)k * dout + t];
        biasx[t] = a;
    }
}

// ---------------- fp16 mma GEMM: 128x128 tile (round-7 shell), dual-pointer A,
// ---------------- fused BN stats in epilogue ----------------
#define GSTR 40
#define TILE_B (128 * GSTR * 2)   // 10240 bytes per array tile
#define STG_B (2 * TILE_B)        // A|B = 20480
#define GSMEM (2 * STG_B)         // 40960

__global__ void __launch_bounds__(256, 2)
gemm_h(const __half* __restrict__ Aroot, const __half* __restrict__ Aagg,
       const __half* __restrict__ B, __half* __restrict__ actOut,
       const float* __restrict__ biasx, float* __restrict__ sum, float* __restrict__ sumsq,
       int Kseg, int rootStride, int aggW, int Kpad, int dout, int strideOut) {
    extern __shared__ char smem[];
    uint32_t sb = smem_u32(smem);
    const int tid = threadIdx.x;
    const int wid = tid >> 5, lane = tid & 31;
    const int bm = blockIdx.y * 128;
    const int bnb = blockIdx.x * 128;
    const int mbase = (wid >> 2) * 64;
    const int nbase = (wid & 3) * 32;

    const int rA = (lane & 7) + ((lane >> 3) & 1) * 8;
    const int kA = (lane >> 4) * 8;
    const int rB = (lane & 7) + ((lane >> 4) & 1) * 8;
    const int kB = ((lane >> 3) & 1) * 8;

    float acc[4][4][4];
#pragma unroll
    for (int mi = 0; mi < 4; mi++)
#pragma unroll
        for (int ni = 0; ni < 4; ni++)
#pragma unroll
            for (int e = 0; e < 4; e++) acc[mi][ni][e] = 0.f;

    const int nIter = Kpad >> 5;
    const size_t KpadB = (size_t)Kpad * 2;

    const int lrow0 = tid >> 2, lc0 = (tid & 3);
    const int lrow1 = (tid + 256) >> 2;
#define LOAD_STAGE(it, stg)                                                               \
    {                                                                                     \
        int kt = (it)*32;                                                                 \
        const char* abase;                                                                \
        size_t rstride;                                                                   \
        if (kt < Kseg) {                                                                  \
            abase = (const char*)Aroot + (size_t)kt * 2;                                  \
            rstride = (size_t)rootStride * 2;                                             \
        } else {                                                                          \
            abase = (const char*)Aagg + (size_t)(kt - Kseg) * 2;                          \
            rstride = (size_t)aggW * 2;                                                   \
        }                                                                                 \
        uint32_t sdst = sb + (stg)*STG_B;                                                 \
        CP_ASYNC16(sdst + lrow0 * 80 + lc0 * 16,                                          \
                   abase + (size_t)(bm + lrow0) * rstride + lc0 * 16);                    \
        CP_ASYNC16(sdst + lrow1 * 80 + lc0 * 16,                                          \
                   abase + (size_t)(bm + lrow1) * rstride + lc0 * 16);                    \
        const char* bbase = (const char*)B + (size_t)kt * 2;                              \
        CP_ASYNC16(sdst + TILE_B + lrow0 * 80 + lc0 * 16,                                 \
                   bbase + (size_t)(bnb + lrow0) * KpadB + lc0 * 16);                     \
        CP_ASYNC16(sdst + TILE_B + lrow1 * 80 + lc0 * 16,                                 \
                   bbase + (size_t)(bnb + lrow1) * KpadB + lc0 * 16);                     \
    }

    LOAD_STAGE(0, 0);
    CP_COMMIT();

    for (int i = 0; i < nIter; i++) {
        if (i + 1 < nIter) {
            LOAD_STAGE(i + 1, (i + 1) & 1);
            CP_COMMIT();
            CP_WAIT(1);
        } else {
            CP_WAIT(0);
        }
        __syncthreads();

        uint32_t st = sb + (i & 1) * STG_B;
        uint32_t sA_t = st + ((mbase + rA) * GSTR + kA) * 2;
        uint32_t sB_t = st + TILE_B + ((nbase + rB) * GSTR + kB) * 2;

#pragma unroll
        for (int kk = 0; kk < 2; kk++) {
            uint32_t koff = kk * 32;
            uint32_t Af[4][4], Bf[4][2];
#pragma unroll
            for (int mi = 0; mi < 4; mi++)
                ldm4(Af[mi], sA_t + mi * 16 * GSTR * 2 + koff);
            {
                uint32_t t0[4], t1[4];
                ldm4(t0, sB_t + koff);
                ldm4(t1, sB_t + 16 * GSTR * 2 + koff);
                Bf[0][0] = t0[0]; Bf[0][1] = t0[1]; Bf[1][0] = t0[2]; Bf[1][1] = t0[3];
                Bf[2][0] = t1[0]; Bf[2][1] = t1[1]; Bf[3][0] = t1[2]; Bf[3][1] = t1[3];
            }
#pragma unroll
            for (int mi = 0; mi < 4; mi++)
#pragma unroll
                for (int ni = 0; ni < 4; ni++) mma_f16(acc[mi][ni], Af[mi], Bf[ni]);
        }
        __syncthreads();
    }

    // epilogue: fp16 store (+biasx, zero-pad) with fused BN stats
    const int grp = lane >> 2, q = lane & 3;
#pragma unroll
    for (int ni = 0; ni < 4; ni++) {
        int gc = bnb + nbase + ni * 8 + q * 2;
        float bx0 = (gc < dout) ? biasx[gc] : 0.f;
        float bx1 = (gc + 1 < dout) ? biasx[gc + 1] : 0.f;
        float t0 = 0.f, t1 = 0.f, u0 = 0.f, u1 = 0.f;
#pragma unroll
        for (int mi = 0; mi < 4; mi++) {
#pragma unroll
            for (int hf = 0; hf < 2; hf++) {
                int m = bm + mbase + mi * 16 + grp + hf * 8;
                if (m >= NN) continue;
                float o0 = (gc < dout) ? acc[mi][ni][hf * 2] + bx0 : 0.f;
                float o1 = (gc + 1 < dout) ? acc[mi][ni][hf * 2 + 1] + bx1 : 0.f;
                if (gc < strideOut)
                    *(__half2*)(actOut + (size_t)m * strideOut + gc) =
                        __floats2half2_rn(o0, o1);
                t0 += o0; u0 += o0 * o0;
                t1 += o1; u1 += o1 * o1;
            }
        }
#pragma unroll
        for (int d = 4; d < 32; d <<= 1) {
            t0 += __shfl_xor_sync(0xffffffffu, t0, d);
            t1 += __shfl_xor_sync(0xffffffffu, t1, d);
            u0 += __shfl_xor_sync(0xffffffffu, u0, d);
            u1 += __shfl_xor_sync(0xffffffffu, u1, d);
        }
        if (grp == 0 && gc < dout) {
            REDADD(&sum[gc], t0);
            REDADD(&sumsq[gc], u0);
            if (gc + 1 < dout) {
                REDADD(&sum[gc + 1], t1);
                REDADD(&sumsq[gc + 1], u1);
            }
        }
    }
}

// ---------------- BN finalize ----------------
__global__ void bn_finalize(const float* __restrict__ sum, const float* __restrict__ sumsq,
                            const float* __restrict__ g, const float* __restrict__ bb,
                            float* __restrict__ scale, float* __restrict__ shift, int n) {
    int c = threadIdx.x;
    float invn = 1.0f / (float)n;
    float mu = sum[c] * invn;
    float var = sumsq[c] * invn - mu * mu;
    float sc = g[c] * rsqrtf(var + BN_EPS);
    scale[c] = sc;
    shift[c] = bb[c] - mu * sc;
}

// ---------------- pooling (final BN fused) ----------------
__global__ void __launch_bounds__(256)
pool_kernel(const __half* __restrict__ x, const int* __restrict__ batch,
            const float* __restrict__ scale, const float* __restrict__ shift,
            float* __restrict__ pool, int* __restrict__ pcnt) {
    int row = blockIdx.x * 8 + (threadIdx.x >> 5);
    if (row >= NN) return;
    int lane = threadIdx.x & 31;
    int g = batch[row];
    const __half* in = x + (size_t)row * 256;
    float* op = pool + (size_t)g * 256;
    for (int c = lane * 4; c < 256; c += 128) {
        float4 v = ld_h4(in + c);
        v.x = v.x * scale[c] + shift[c];
        v.y = v.y * scale[c + 1] + shift[c + 1];
        v.z = v.z * scale[c + 2] + shift[c + 2];
        v.w = v.w * scale[c + 3] + shift[c + 3];
        asm volatile("red.global.add.v4.f32 [%0], {%1,%2,%3,%4};" ::"l"(op + c),
                     "f"(v.x), "f"(v.y), "f"(v.z), "f"(v.w)
                     : "memory");
    }
    if (lane == 0) atomicAdd(&pcnt[g], 1);
}

// ---------------- final MLP head ----------------
__global__ void final_kernel(const float* __restrict__ pool, const int* __restrict__ pcnt,
                             const float* __restrict__ meta, const float* __restrict__ l1w,
                             const float* __restrict__ l1b, const float* __restrict__ l2w,
                             const float* __restrict__ l2b, float* __restrict__ out) {
    __shared__ float cv[256 + METAD];
    __shared__ float red[128];
    int g = blockIdx.x;
    int t = threadIdx.x;
    float invc = 1.0f / fmaxf((float)pcnt[g], 1.0f);
    for (int c = t; c < 256 + METAD; c += 128)
        cv[c] = (c < 256) ? pool[g * 256 + c] * invc : meta[g * METAD + (c - 256)];
    __syncthreads();
    float val = 0.f;
    if (t < 100) {
        float a = l1b[t];
        for (int i = 0; i < 256 + METAD; i++) a += cv[i] * l1w[i * 100 + t];
        val = a * l2w[t];
    }
    red[t] = val;
    __syncthreads();
    for (int s = 64; s > 0; s >>= 1) {
        if (t < s) red[t] += red[t + s];
        __syncthreads();
    }
    if (t == 0) out[g] = red[0] + l2b[0];
}

// ---------------- host driver ----------------
struct Ptrs {
    __half *Ah, *Bh, *x16, *actA, *actB;
    float *biasx, *sum, *sumsq, *scale, *shift, *pool;
    int *cnt, *off, *cur, *esrc, *bsum, *pcnt;
};

static void run_layer(const __half* actIn, int actStride, const float* scaleIn,
                      const float* shiftIn, int din, int Kseg, int dout, int strideOut,
                      int Npad, const float* W, const float* Rw, const float* b,
                      const float* gm, const float* bt, __half* actOut, const Ptrs& P) {
    int aggW = 3 * Kseg + 32;
    int Kpad = 4 * Kseg + 32;
    agg_kernel<<<(RN + 7) / 8, 256>>>(P.esrc, P.off, P.cnt, actIn, P.Ah, din, actStride,
                                      Kseg, aggW);
    convB_h<<<(256 * Kpad + 255) / 256, 256>>>(W, Rw, scaleIn, shiftIn, P.Bh, din, Kseg,
                                               Kpad, dout);
    prep_kernel<<<1, 256>>>(b, Rw, shiftIn, P.biasx, P.sum, P.sumsq, din, dout);
    dim3 grid(Npad / 128, MPAD / 128);
    gemm_h<<<grid, 256, GSMEM>>>(actIn, P.Ah, P.Bh, actOut, P.biasx, P.sum, P.sumsq, Kseg,
                                 actStride, aggW, Kpad, dout, strideOut);
    bn_finalize<<<1, dout>>>(P.sum, P.sumsq, gm, bt, P.scale, P.shift, NN);
}

extern "C" void kernel_launch(void* const* d_in, const int* in_sizes, int n_in,
                              void* d_out, int out_size) {
    const float* x = (const float*)d_in[0];
    const int* ei = (const int*)d_in[2];
    const int* et = (const int*)d_in[3];
    const float* meta = (const float*)d_in[4];
    const int* batch = (const int*)d_in[5];
    const float* W[4];
    const float* Rw[4];
    const float* b[4];
    const float* gm[4];
    const float* bt[4];
    int idx = 6;
    for (int l = 0; l < 4; l++) {
        W[l] = (const float*)d_in[idx++];
        Rw[l] = (const float*)d_in[idx++];
        b[l] = (const float*)d_in[idx++];
        gm[l] = (const float*)d_in[idx++];
        bt[l] = (const float*)d_in[idx++];
    }
    const float* l1w = (const float*)d_in[26];
    const float* l1b = (const float*)d_in[27];
    const float* l2w = (const float*)d_in[28];
    const float* l2b = (const float*)d_in[29];
    float* out = (float*)d_out;

    Ptrs P;
    cudaGetSymbolAddress((void**)&P.Ah, g_Ah);
    cudaGetSymbolAddress((void**)&P.Bh, g_Bh);
    cudaGetSymbolAddress((void**)&P.x16, g_x16);
    cudaGetSymbolAddress((void**)&P.actA, g_actA);
    cudaGetSymbolAddress((void**)&P.actB, g_actB);
    cudaGetSymbolAddress((void**)&P.biasx, g_biasx);
    cudaGetSymbolAddress((void**)&P.cnt, g_cnt);
    cudaGetSymbolAddress((void**)&P.off, g_off);
    cudaGetSymbolAddress((void**)&P.cur, g_cur);
    cudaGetSymbolAddress((void**)&P.esrc, g_esrc);
    cudaGetSymbolAddress((void**)&P.bsum, g_bsum);
    cudaGetSymbolAddress((void**)&P.sum, g_sum);
    cudaGetSymbolAddress((void**)&P.sumsq, g_sumsq);
    cudaGetSymbolAddress((void**)&P.scale, g_scale);
    cudaGetSymbolAddress((void**)&P.shift, g_shift);
    cudaGetSymbolAddress((void**)&P.pool, g_pool);
    cudaGetSymbolAddress((void**)&P.pcnt, g_pcnt);

    cudaFuncSetAttribute(gemm_h, cudaFuncAttributeMaxDynamicSharedMemorySize, GSMEM);

    // CSR build (input-constant per call)
    zero_i<<<256, 256>>>(P.cnt, RN);
    zero_i<<<256, 256>>>(P.cur, RN);
    count_kernel<<<(EE + 255) / 256, 256>>>(ei, et, P.cnt);
    int nb = (RN + 1023) / 1024;  // 147
    scan1<<<nb, 256>>>(P.cnt, P.off, P.bsum, RN);
    scan2<<<1, 256>>>(P.bsum, nb);
    scan3<<<(RN + 255) / 256, 256>>>(P.off, P.bsum, RN);
    fill_kernel<<<(EE + 255) / 256, 256>>>(ei, et, P.off, P.cur, P.esrc);

    // input -> fp16 once (pad rows of g_x16 stay 0)
    conv_x<<<(NN * 64 + 255) / 256, 256>>>(x, P.x16, NN * 64);

    // 4 RGCN layers (aggregate-first, BN folded into B + indicator chunk)
    //        actIn   stride  scale    shift    din  Kseg dout sOut Npad
    run_layer(P.x16,  128,    nullptr, nullptr, 128, 128, 100, 128, 128, W[0], Rw[0],
              b[0], gm[0], bt[0], P.actA, P);
    run_layer(P.actA, 128,    P.scale, P.shift, 100, 128, 256, 256, 256, W[1], Rw[1],
              b[1], gm[1], bt[1], P.actB, P);
    run_layer(P.actB, 256,    P.scale, P.shift, 256, 256, 256, 256, 256, W[2], Rw[2],
              b[2], gm[2], bt[2], P.actA, P);
    run_layer(P.actA, 256,    P.scale, P.shift, 256, 256, 256, 256, 256, W[3], Rw[3],
              b[3], gm[3], bt[3], P.actB, P);

    // global mean pool (final BN fused) + MLP head
    zero_f<<<64, 256>>>(P.pool, GG * 256);
    zero_i<<<1, 64>>>(P.pcnt, GG);
    pool_kernel<<<(NN + 7) / 8, 256>>>(P.actB, batch, P.scale, P.shift, P.pool, P.pcnt);
    final_kernel<<<GG, 128>>>(P.pool, P.pcnt, meta, l1w, l1b, l2w, l2b, out);
}

// round 12
// speedup vs baseline: 1.4153x; 1.1669x over previous
#include <cuda_runtime.h>
#include <cuda_fp16.h>
#include <cstdint>

#define NN 50000
#define MPAD 50048
#define EE 800000
#define GG 64
#define RRL 3
#define RN (RRL * NN)
#define METAD 38
#define BN_EPS 1e-5f

// ---------------- scratch (device globals; no allocation; 256B aligned) ----------------
__device__ __align__(256) __half g_Ah[MPAD * 800];    // agg segments (aggW = 3*Kseg)
__device__ __align__(256) __half g_Bh[256 * 1088];    // B: [256, Kpad] fp16 K-major
__device__ __align__(256) __half g_x16[MPAD * 128];   // input x fp16 (pad rows stay 0)
__device__ __align__(256) __half g_actA[MPAD * 256];  // ping (pre-BN activations)
__device__ __align__(256) __half g_actB[MPAD * 256];  // pong
__device__ __align__(256) float g_biasx[256];
__device__ __align__(256) int   g_cnt[RN];
__device__ __align__(256) int   g_off[RN];
__device__ __align__(256) int   g_cur[RN];
__device__ __align__(256) int   g_esrc[EE];
__device__ __align__(256) int   g_bsum[256];
__device__ __align__(256) float g_sum[256];
__device__ __align__(256) float g_sumsq[256];
__device__ __align__(256) float g_scale[256];
__device__ __align__(256) float g_shift[256];
__device__ __align__(256) float g_sos[256];           // shift/scale
__device__ __align__(256) float g_pool[GG * 256];
__device__ __align__(256) int   g_pcnt[GG];

// ---------------- PTX helpers ----------------
__device__ __forceinline__ uint32_t smem_u32(const void* p) {
    uint32_t a;
    asm("{ .reg .u64 t; cvta.to.shared.u64 t, %1; cvt.u32.u64 %0, t; }" : "=r"(a) : "l"(p));
    return a;
}
__device__ __forceinline__ void ldm4(uint32_t* r, uint32_t addr) {
    asm volatile("ldmatrix.sync.aligned.m8n8.x4.shared.b16 {%0,%1,%2,%3}, [%4];"
                 : "=r"(r[0]), "=r"(r[1]), "=r"(r[2]), "=r"(r[3]) : "r"(addr));
}
__device__ __forceinline__ void mma_f16(float* d, const uint32_t* a, const uint32_t* b) {
    asm volatile(
        "mma.sync.aligned.m16n8k16.row.col.f32.f16.f16.f32 "
        "{%0,%1,%2,%3}, {%4,%5,%6,%7}, {%8,%9}, {%0,%1,%2,%3};"
        : "+f"(d[0]), "+f"(d[1]), "+f"(d[2]), "+f"(d[3])
        : "r"(a[0]), "r"(a[1]), "r"(a[2]), "r"(a[3]), "r"(b[0]), "r"(b[1]));
}
#define CP_ASYNC16(dst, src) \
    asm volatile("cp.async.cg.shared.global [%0], [%1], 16;" ::"r"(dst), "l"(src))
#define CP_COMMIT() asm volatile("cp.async.commit_group;" ::: "memory")
#define CP_WAIT(n) asm volatile("cp.async.wait_group %0;" ::"n"(n) : "memory")
#define REDADD(p, v) \
    asm volatile("red.global.add.f32 [%0], %1;" ::"l"(p), "f"(v) : "memory")

__device__ __forceinline__ float4 ld_h4(const __half* p) {
    uint2 raw = *(const uint2*)p;
    __half2 h0 = *reinterpret_cast<__half2*>(&raw.x);
    __half2 h1 = *reinterpret_cast<__half2*>(&raw.y);
    float2 f0 = __half22float2(h0), f1 = __half22float2(h1);
    return make_float4(f0.x, f0.y, f1.x, f1.y);
}
__device__ __forceinline__ void st_h4(__half* p, float4 v) {
    uint2 raw;
    __half2 h0 = __floats2half2_rn(v.x, v.y);
    __half2 h1 = __floats2half2_rn(v.z, v.w);
    raw.x = *reinterpret_cast<uint32_t*>(&h0);
    raw.y = *reinterpret_cast<uint32_t*>(&h1);
    *(uint2*)p = raw;
}

// ---------------- utility kernels ----------------
__global__ void zero_f(float* p, int n) {
    for (int i = blockIdx.x * blockDim.x + threadIdx.x; i < n; i += gridDim.x * blockDim.x)
        p[i] = 0.f;
}
__global__ void zero_i(int* p, int n) {
    for (int i = blockIdx.x * blockDim.x + threadIdx.x; i < n; i += gridDim.x * blockDim.x)
        p[i] = 0;
}
__global__ void count_kernel(const int* __restrict__ ei, const int* __restrict__ et,
                             int* __restrict__ cnt) {
    int e = blockIdx.x * blockDim.x + threadIdx.x;
    if (e >= EE) return;
    atomicAdd(&cnt[et[e] * NN + ei[EE + e]], 1);
}
__global__ void conv_x(const float* __restrict__ x, __half* __restrict__ x16, int n) {
    int i = blockIdx.x * blockDim.x + threadIdx.x;
    if (i < n) {
        float2 v = ((const float2*)x)[i];
        ((__half2*)x16)[i] = __floats2half2_rn(v.x, v.y);
    }
}

// ---------------- CSR build ----------------
__global__ void scan1(const int* __restrict__ cnt, int* __restrict__ off,
                      int* __restrict__ bsum, int n) {
    __shared__ int sh[256];
    int tid = threadIdx.x;
    int base = blockIdx.x * 1024;
    int vals[4], tsum = 0;
#pragma unroll
    for (int j = 0; j < 4; j++) {
        int i = base + tid * 4 + j;
        vals[j] = (i < n) ? cnt[i] : 0;
        tsum += vals[j];
    }
    sh[tid] = tsum;
    __syncthreads();
    for (int d = 1; d < 256; d <<= 1) {
        int v = (tid >= d) ? sh[tid - d] : 0;
        __syncthreads();
        sh[tid] += v;
        __syncthreads();
    }
    int run = sh[tid] - tsum;
#pragma unroll
    for (int j = 0; j < 4; j++) {
        int i = base + tid * 4 + j;
        if (i < n) off[i] = run;
        run += vals[j];
    }
    if (tid == 255) bsum[blockIdx.x] = sh[255];
}
__global__ void scan2(int* __restrict__ bsum, int nb) {
    __shared__ int sh[256];
    int tid = threadIdx.x;
    int v = (tid < nb) ? bsum[tid] : 0;
    sh[tid] = v;
    __syncthreads();
    for (int d = 1; d < 256; d <<= 1) {
        int u = (tid >= d) ? sh[tid - d] : 0;
        __syncthreads();
        sh[tid] += u;
        __syncthreads();
    }
    if (tid < nb) bsum[tid] = sh[tid] - v;
}
__global__ void scan3(int* __restrict__ off, const int* __restrict__ bsum, int n) {
    int i = blockIdx.x * blockDim.x + threadIdx.x;
    if (i < n) off[i] += bsum[i >> 10];
}
__global__ void fill_kernel(const int* __restrict__ ei, const int* __restrict__ et,
                            const int* __restrict__ off, int* __restrict__ cur,
                            int* __restrict__ esrc) {
    int e = blockIdx.x * blockDim.x + threadIdx.x;
    if (e >= EE) return;
    int seg = et[e] * NN + ei[EE + e];
    int p = off[seg] + atomicAdd(&cur[seg], 1);
    esrc[p] = ei[e];
}

// ---------------- aggregation: warp per (r,dst), mean + shift/scale fold ------------
__global__ void __launch_bounds__(256)
agg_kernel(const int* __restrict__ esrc, const int* __restrict__ off,
           const int* __restrict__ cnt, const __half* __restrict__ act,
           const float* __restrict__ sos, __half* __restrict__ Ah, int din,
           int actStride, int Kseg, int aggW) {
    int s = blockIdx.x * 8 + (threadIdx.x >> 5);
    if (s >= RN) return;
    int lane = threadIdx.x & 31;
    int r = s / NN, dst = s - r * NN;
    int st = off[s], c_ = cnt[s];
    int e = st + c_;
    __half* out = Ah + (size_t)dst * aggW + (size_t)r * Kseg;
    for (int c0 = lane * 4; c0 < Kseg; c0 += 128) {
        float4 a = make_float4(0.f, 0.f, 0.f, 0.f);
        if (c0 < din && c_ > 0) {
            float4 b = make_float4(0.f, 0.f, 0.f, 0.f);
            int i = st;
            for (; i + 2 <= e; i += 2) {
                int s0 = esrc[i], s1 = esrc[i + 1];
                float4 v0 = ld_h4(act + (size_t)s0 * actStride + c0);
                float4 v1 = ld_h4(act + (size_t)s1 * actStride + c0);
                a.x += v0.x; a.y += v0.y; a.z += v0.z; a.w += v0.w;
                b.x += v1.x; b.y += v1.y; b.z += v1.z; b.w += v1.w;
            }
            if (i < e) {
                float4 v0 = ld_h4(act + (size_t)esrc[i] * actStride + c0);
                a.x += v0.x; a.y += v0.y; a.z += v0.z; a.w += v0.w;
            }
            a.x += b.x; a.y += b.y; a.z += b.z; a.w += b.w;
            float inv = 1.0f / (float)c_;
            a.x *= inv; a.y *= inv; a.z *= inv; a.w *= inv;
            if (sos) {  // fold BN shift: (mean + shift/scale); B carries scale*W
                a.x += sos[c0];
                a.y += sos[c0 + 1];
                a.z += sos[c0 + 2];
                a.w += sos[c0 + 3];
            }
        }
        st_h4(out + c0, a);
    }
}

// ---------------- B build: scale-folded [Rw; W0; W1; W2]; block 0 also does prep ----
__global__ void convB_h(const float* __restrict__ Wrel, const float* __restrict__ Wroot,
                        const float* __restrict__ scale, const float* __restrict__ shift,
                        const float* __restrict__ b, __half* __restrict__ Bh,
                        float* __restrict__ biasx, float* __restrict__ sum,
                        float* __restrict__ sumsq, int din, int Kseg, int Kpad, int dout) {
    int idx = blockIdx.x * blockDim.x + threadIdx.x;
    if (blockIdx.x == 0) {  // fused prep: biasx = b + shift@Rw; zero stat accumulators
        int t = threadIdx.x;
        sum[t] = 0.f;
        sumsq[t] = 0.f;
        if (t < dout) {
            float a = b[t];
            if (shift)
                for (int k = 0; k < din; k++) a += shift[k] * Wroot[(size_t)k * dout + t];
            biasx[t] = a;
        }
    }
    if (idx >= 256 * Kpad) return;
    int n = idx / Kpad;
    int k = idx - n * Kpad;
    float v = 0.f;
    if (n < dout) {
        int seg = k / Kseg, kk = k - seg * Kseg;
        if (kk < din) {
            float w = (seg == 0) ? Wroot[(size_t)kk * dout + n]
                                 : Wrel[((size_t)(seg - 1) * din + kk) * dout + n];
            if (scale) w *= scale[kk];
            v = w;
        }
    }
    Bh[idx] = __float2half(v);
}

// ---------------- fp16 mma GEMM: 128x128 tile, BK=64, dual-pointer A, fused stats ----
#define GSTR 72                    // halfs per smem row (64 + 8 pad)
#define TILE_B (128 * GSTR * 2)    // 18432 bytes
#define STG_B (2 * TILE_B)         // 36864
#define GSMEM (2 * STG_B)          // 73728

__global__ void __launch_bounds__(256, 2)
gemm_h(const __half* __restrict__ Aroot, const __half* __restrict__ Aagg,
       const __half* __restrict__ B, __half* __restrict__ actOut,
       const float* __restrict__ biasx, float* __restrict__ sum, float* __restrict__ sumsq,
       int Kseg, int rootStride, int aggW, int Kpad, int dout, int strideOut) {
    extern __shared__ char smem[];
    uint32_t sb = smem_u32(smem);
    const int tid = threadIdx.x;
    const int wid = tid >> 5, lane = tid & 31;
    const int bm = blockIdx.y * 128;
    const int bnb = blockIdx.x * 128;
    const int mbase = (wid >> 2) * 64;
    const int nbase = (wid & 3) * 32;

    const int rA = (lane & 7) + ((lane >> 3) & 1) * 8;
    const int kA = (lane >> 4) * 8;
    const int rB = (lane & 7) + ((lane >> 4) & 1) * 8;
    const int kB = ((lane >> 3) & 1) * 8;

    float acc[4][4][4];
#pragma unroll
    for (int mi = 0; mi < 4; mi++)
#pragma unroll
        for (int ni = 0; ni < 4; ni++)
#pragma unroll
            for (int e = 0; e < 4; e++) acc[mi][ni][e] = 0.f;

    const int nIter = Kpad >> 6;  // BK=64
    const size_t KpadB = (size_t)Kpad * 2;

#define LOAD_STAGE(it, stg)                                                               \
    {                                                                                     \
        int kt = (it)*64;                                                                 \
        const char* abase;                                                                \
        size_t rstride;                                                                   \
        if (kt < Kseg) {                                                                  \
            abase = (const char*)Aroot + (size_t)kt * 2;                                  \
            rstride = (size_t)rootStride * 2;                                             \
        } else {                                                                          \
            abase = (const char*)Aagg + (size_t)(kt - Kseg) * 2;                          \
            rstride = (size_t)aggW * 2;                                                   \
        }                                                                                 \
        uint32_t sdst = sb + (stg)*STG_B;                                                 \
        const char* bbase = (const char*)B + (size_t)kt * 2;                              \
        _Pragma("unroll") for (int t = 0; t < 4; t++) {                                   \
            int idx2 = tid + t * 256;                                                     \
            int row = idx2 >> 3, c = idx2 & 7;                                            \
            CP_ASYNC16(sdst + row * 144 + c * 16,                                         \
                       abase + (size_t)(bm + row) * rstride + c * 16);                    \
            CP_ASYNC16(sdst + TILE_B + row * 144 + c * 16,                                \
                       bbase + (size_t)(bnb + row) * KpadB + c * 16);                     \
        }                                                                                 \
    }

    LOAD_STAGE(0, 0);
    CP_COMMIT();

    for (int i = 0; i < nIter; i++) {
        if (i + 1 < nIter) {
            LOAD_STAGE(i + 1, (i + 1) & 1);
            CP_COMMIT();
            CP_WAIT(1);
        } else {
            CP_WAIT(0);
        }
        __syncthreads();

        uint32_t st = sb + (i & 1) * STG_B;
        uint32_t sA_t = st + ((mbase + rA) * GSTR + kA) * 2;
        uint32_t sB_t = st + TILE_B + ((nbase + rB) * GSTR + kB) * 2;

#pragma unroll
        for (int kk = 0; kk < 4; kk++) {  // four k16 steps in BK=64
            uint32_t koff = kk * 32;
            uint32_t Af[4][4], Bf[4][2];
#pragma unroll
            for (int mi = 0; mi < 4; mi++)
                ldm4(Af[mi], sA_t + mi * 16 * GSTR * 2 + koff);
            {
                uint32_t t0[4], t1[4];
                ldm4(t0, sB_t + koff);
                ldm4(t1, sB_t + 16 * GSTR * 2 + koff);
                Bf[0][0] = t0[0]; Bf[0][1] = t0[1]; Bf[1][0] = t0[2]; Bf[1][1] = t0[3];
                Bf[2][0] = t1[0]; Bf[2][1] = t1[1]; Bf[3][0] = t1[2]; Bf[3][1] = t1[3];
            }
#pragma unroll
            for (int mi = 0; mi < 4; mi++)
#pragma unroll
                for (int ni = 0; ni < 4; ni++) mma_f16(acc[mi][ni], Af[mi], Bf[ni]);
        }
        __syncthreads();
    }

    // epilogue: fp16 store (+biasx, zero-pad) with fused BN stats
    const int grp = lane >> 2, q = lane & 3;
#pragma unroll
    for (int ni = 0; ni < 4; ni++) {
        int gc = bnb + nbase + ni * 8 + q * 2;
        float bx0 = (gc < dout) ? biasx[gc] : 0.f;
        float bx1 = (gc + 1 < dout) ? biasx[gc + 1] : 0.f;
        float t0 = 0.f, t1 = 0.f, u0 = 0.f, u1 = 0.f;
#pragma unroll
        for (int mi = 0; mi < 4; mi++) {
#pragma unroll
            for (int hf = 0; hf < 2; hf++) {
                int m = bm + mbase + mi * 16 + grp + hf * 8;
                if (m >= NN) continue;
                float o0 = (gc < dout) ? acc[mi][ni][hf * 2] + bx0 : 0.f;
                float o1 = (gc + 1 < dout) ? acc[mi][ni][hf * 2 + 1] + bx1 : 0.f;
                if (gc < strideOut)
                    *(__half2*)(actOut + (size_t)m * strideOut + gc) =
                        __floats2half2_rn(o0, o1);
                t0 += o0; u0 += o0 * o0;
                t1 += o1; u1 += o1 * o1;
            }
        }
#pragma unroll
        for (int d = 4; d < 32; d <<= 1) {
            t0 += __shfl_xor_sync(0xffffffffu, t0, d);
            t1 += __shfl_xor_sync(0xffffffffu, t1, d);
            u0 += __shfl_xor_sync(0xffffffffu, u0, d);
            u1 += __shfl_xor_sync(0xffffffffu, u1, d);
        }
        if (grp == 0 && gc < dout) {
            REDADD(&sum[gc], t0);
            REDADD(&sumsq[gc], u0);
            if (gc + 1 < dout) {
                REDADD(&sum[gc + 1], t1);
                REDADD(&sumsq[gc + 1], u1);
            }
        }
    }
}

// ---------------- BN finalize (+ shift/scale for next layer's agg fold) ----------------
__global__ void bn_finalize(const float* __restrict__ sum, const float* __restrict__ sumsq,
                            const float* __restrict__ g, const float* __restrict__ bb,
                            float* __restrict__ scale, float* __restrict__ shift,
                            float* __restrict__ sos, int n) {
    int c = threadIdx.x;
    float invn = 1.0f / (float)n;
    float mu = sum[c] * invn;
    float var = sumsq[c] * invn - mu * mu;
    float sc = g[c] * rsqrtf(var + BN_EPS);
    float sh = bb[c] - mu * sc;
    scale[c] = sc;
    shift[c] = sh;
    sos[c] = (sc != 0.f) ? sh / sc : 0.f;
}

// ---------------- pooling (final BN fused) ----------------
__global__ void __launch_bounds__(256)
pool_kernel(const __half* __restrict__ x, const int* __restrict__ batch,
            const float* __restrict__ scale, const float* __restrict__ shift,
            float* __restrict__ pool, int* __restrict__ pcnt) {
    int row = blockIdx.x * 8 + (threadIdx.x >> 5);
    if (row >= NN) return;
    int lane = threadIdx.x & 31;
    int g = batch[row];
    const __half* in = x + (size_t)row * 256;
    float* op = pool + (size_t)g * 256;
    for (int c = lane * 4; c < 256; c += 128) {
        float4 v = ld_h4(in + c);
        v.x = v.x * scale[c] + shift[c];
        v.y = v.y * scale[c + 1] + shift[c + 1];
        v.z = v.z * scale[c + 2] + shift[c + 2];
        v.w = v.w * scale[c + 3] + shift[c + 3];
        asm volatile("red.global.add.v4.f32 [%0], {%1,%2,%3,%4};" ::"l"(op + c),
                     "f"(v.x), "f"(v.y), "f"(v.z), "f"(v.w)
                     : "memory");
    }
    if (lane == 0) atomicAdd(&pcnt[g], 1);
}

// ---------------- final MLP head ----------------
__global__ void final_kernel(const float* __restrict__ pool, const int* __restrict__ pcnt,
                             const float* __restrict__ meta, const float* __restrict__ l1w,
                             const float* __restrict__ l1b, const float* __restrict__ l2w,
                             const float* __restrict__ l2b, float* __restrict__ out) {
    __shared__ float cv[256 + METAD];
    __shared__ float red[128];
    int g = blockIdx.x;
    int t = threadIdx.x;
    float invc = 1.0f / fmaxf((float)pcnt[g], 1.0f);
    for (int c = t; c < 256 + METAD; c += 128)
        cv[c] = (c < 256) ? pool[g * 256 + c] * invc : meta[g * METAD + (c - 256)];
    __syncthreads();
    float val = 0.f;
    if (t < 100) {
        float a = l1b[t];
        for (int i = 0; i < 256 + METAD; i++) a += cv[i] * l1w[i * 100 + t];
        val = a * l2w[t];
    }
    red[t] = val;
    __syncthreads();
    for (int s = 64; s > 0; s >>= 1) {
        if (t < s) red[t] += red[t + s];
        __syncthreads();
    }
    if (t == 0) out[g] = red[0] + l2b[0];
}

// ---------------- host driver ----------------
struct Ptrs {
    __half *Ah, *Bh, *x16, *actA, *actB;
    float *biasx, *sum, *sumsq, *scale, *shift, *sos, *pool;
    int *cnt, *off, *cur, *esrc, *bsum, *pcnt;
};

static void run_layer(const __half* actIn, int actStride, const float* scaleIn,
                      const float* shiftIn, const float* sosIn, int din, int Kseg,
                      int dout, int strideOut, int Npad, const float* W, const float* Rw,
                      const float* b, const float* gm, const float* bt, __half* actOut,
                      const Ptrs& P) {
    int aggW = 3 * Kseg;
    int Kpad = 4 * Kseg;
    agg_kernel<<<(RN + 7) / 8, 256>>>(P.esrc, P.off, P.cnt, actIn, sosIn, P.Ah, din,
                                      actStride, Kseg, aggW);
    convB_h<<<(256 * Kpad + 255) / 256, 256>>>(W, Rw, scaleIn, shiftIn, b, P.Bh, P.biasx,
                                               P.sum, P.sumsq, din, Kseg, Kpad, dout);
    dim3 grid(Npad / 128, MPAD / 128);
    gemm_h<<<grid, 256, GSMEM>>>(actIn, P.Ah, P.Bh, actOut, P.biasx, P.sum, P.sumsq, Kseg,
                                 actStride, aggW, Kpad, dout, strideOut);
    bn_finalize<<<1, dout>>>(P.sum, P.sumsq, gm, bt, P.scale, P.shift, P.sos, NN);
}

extern "C" void kernel_launch(void* const* d_in, const int* in_sizes, int n_in,
                              void* d_out, int out_size) {
    const float* x = (const float*)d_in[0];
    const int* ei = (const int*)d_in[2];
    const int* et = (const int*)d_in[3];
    const float* meta = (const float*)d_in[4];
    const int* batch = (const int*)d_in[5];
    const float* W[4];
    const float* Rw[4];
    const float* b[4];
    const float* gm[4];
    const float* bt[4];
    int idx = 6;
    for (int l = 0; l < 4; l++) {
        W[l] = (const float*)d_in[idx++];
        Rw[l] = (const float*)d_in[idx++];
        b[l] = (const float*)d_in[idx++];
        gm[l] = (const float*)d_in[idx++];
        bt[l] = (const float*)d_in[idx++];
    }
    const float* l1w = (const float*)d_in[26];
    const float* l1b = (const float*)d_in[27];
    const float* l2w = (const float*)d_in[28];
    const float* l2b = (const float*)d_in[29];
    float* out = (float*)d_out;

    Ptrs P;
    cudaGetSymbolAddress((void**)&P.Ah, g_Ah);
    cudaGetSymbolAddress((void**)&P.Bh, g_Bh);
    cudaGetSymbolAddress((void**)&P.x16, g_x16);
    cudaGetSymbolAddress((void**)&P.actA, g_actA);
    cudaGetSymbolAddress((void**)&P.actB, g_actB);
    cudaGetSymbolAddress((void**)&P.biasx, g_biasx);
    cudaGetSymbolAddress((void**)&P.cnt, g_cnt);
    cudaGetSymbolAddress((void**)&P.off, g_off);
    cudaGetSymbolAddress((void**)&P.cur, g_cur);
    cudaGetSymbolAddress((void**)&P.esrc, g_esrc);
    cudaGetSymbolAddress((void**)&P.bsum, g_bsum);
    cudaGetSymbolAddress((void**)&P.sum, g_sum);
    cudaGetSymbolAddress((void**)&P.sumsq, g_sumsq);
    cudaGetSymbolAddress((void**)&P.scale, g_scale);
    cudaGetSymbolAddress((void**)&P.shift, g_shift);
    cudaGetSymbolAddress((void**)&P.sos, g_sos);
    cudaGetSymbolAddress((void**)&P.pool, g_pool);
    cudaGetSymbolAddress((void**)&P.pcnt, g_pcnt);

    cudaFuncSetAttribute(gemm_h, cudaFuncAttributeMaxDynamicSharedMemorySize, GSMEM);

    // CSR build (input-constant per call)
    zero_i<<<256, 256>>>(P.cnt, RN);
    zero_i<<<256, 256>>>(P.cur, RN);
    count_kernel<<<(EE + 255) / 256, 256>>>(ei, et, P.cnt);
    int nb = (RN + 1023) / 1024;  // 147
    scan1<<<nb, 256>>>(P.cnt, P.off, P.bsum, RN);
    scan2<<<1, 256>>>(P.bsum, nb);
    scan3<<<(RN + 255) / 256, 256>>>(P.off, P.bsum, RN);
    fill_kernel<<<(EE + 255) / 256, 256>>>(ei, et, P.off, P.cur, P.esrc);

    // input -> fp16 once (pad rows of g_x16 stay 0)
    conv_x<<<(NN * 64 + 255) / 256, 256>>>(x, P.x16, NN * 64);

    // 4 RGCN layers (aggregate-first, BN folded into B + agg shift fold)
    //        actIn   stride  scale    shift    sos      din  Kseg dout sOut Npad
    run_layer(P.x16,  128,    nullptr, nullptr, nullptr, 128, 128, 100, 128, 128, W[0],
              Rw[0], b[0], gm[0], bt[0], P.actA, P);
    run_layer(P.actA, 128,    P.scale, P.shift, P.sos,   100, 128, 256, 256, 256, W[1],
              Rw[1], b[1], gm[1], bt[1], P.actB, P);
    run_layer(P.actB, 256,    P.scale, P.shift, P.sos,   256, 256, 256, 256, 256, W[2],
              Rw[2], b[2], gm[2], bt[2], P.actA, P);
    run_layer(P.actA, 256,    P.scale, P.shift, P.sos,   256, 256, 256, 256, 256, W[3],
              Rw[3], b[3], gm[3], bt[3], P.actB, P);

    // global mean pool (final BN fused) + MLP head
    zero_f<<<64, 256>>>(P.pool, GG * 256);
    zero_i<<<1, 64>>>(P.pcnt, GG);
    pool_kernel<<<(NN + 7) / 8, 256>>>(P.actB, batch, P.scale, P.shift, P.pool, P.pcnt);
    final_kernel<<<GG, 128>>>(P.pool, P.pcnt, meta, l1w, l1b, l2w, l2b, out);
}